// round 12
// baseline (speedup 1.0000x reference)
#include <cuda_runtime.h>

#define NN 8192
#define CC 128
#define FULLMASK 0xFFFFFFFFu
#define CAP 128
#define BM 32
#define SCANB 1184            // 148 SMs x 8 blocks: exactly one wave
#define TAILB 33

// ---- scratch ----
__device__ float g_h[NN * CC];
__device__ int   g_degi[NN];            // zeroed by k_gemm self-clean (static-init first call)
__device__ int   g_cnt[NN];
__device__ int   g_bkt[NN * CAP];
__device__ float g_BT[2 * CC * CC];     // [Wn^T ; Wc^T], K-major [256][128]
__device__ float g_sum[CC];             // zeroed by k_scan tail block
__device__ float g_sumsq[CC];

__device__ __forceinline__ void ffma2(unsigned long long& d, unsigned long long a, unsigned long long b) {
    asm("fma.rn.f32x2 %0, %1, %2, %0;" : "+l"(d) : "l"(a), "l"(b));
}
__device__ __forceinline__ unsigned long long pack2(float x) {
    unsigned long long r; asm("mov.b64 %0, {%1, %1};" : "=l"(r) : "f"(x)); return r;
}

// ---------------------------------------------------------------
// Kernel 1: tail blocks 0..32 (transpose / stat-zero), scan blocks 33..1216.
// Scan: persistent single wave, rolling 4-deep prefetch window.
__global__ void __launch_bounds__(256, 8)
k_scan(const uint4* __restrict__ A4,
       const float* __restrict__ Wn, const float* __restrict__ Wc) {
    if (blockIdx.x < TAILB) {
        int bid = blockIdx.x;
        if (bid == 32) {
            if (threadIdx.x < CC) { g_sum[threadIdx.x] = 0.f; g_sumsq[threadIdx.x] = 0.f; }
            return;
        }
        __shared__ float s[32][33];
        int m = bid >> 4;
        int t = bid & 15;
        int tr = (t >> 2) * 32;
        int tc = (t & 3) * 32;
        const float* src = m ? Wc : Wn;
        float* dst = g_BT + m * CC * CC;
        int x = threadIdx.x & 31;
        int y0 = threadIdx.x >> 5;
#pragma unroll
        for (int dy = 0; dy < 32; dy += 8)
            s[y0 + dy][x] = src[(tr + y0 + dy) * CC + tc + x];
        __syncthreads();
#pragma unroll
        for (int dy = 0; dy < 32; dy += 8)
            dst[(tc + y0 + dy) * CC + tr + x] = s[x][y0 + dy];
        return;
    }

    const int lane = threadIdx.x & 31;
    const unsigned step  = SCANB * 256u;       // 303104
    const unsigned total = 16777216u;          // NN * 2048 uint4
    const unsigned q = (blockIdx.x - TAILB) * 256u + threadIdx.x;

    uint4 v[4];
#pragma unroll
    for (int u = 0; u < 4; ++u) {
        unsigned qu = q + u * step;
        v[u] = (qu < total) ? __ldcs(&A4[qu]) : make_uint4(0u, 0u, 0u, 0u);
    }

#pragma unroll 4
    for (int it = 0; it < 56; ++it) {
        const int slot = it & 3;
        uint4 w = v[slot];
        // refill the slot 4 steps ahead (keeps ~4 loads always in flight)
        {
            unsigned qp = q + (unsigned)(it + 4) * step;
            v[slot] = (it + 4 < 56 && qp < total) ? __ldcs(&A4[qp])
                                                  : make_uint4(0u, 0u, 0u, 0u);
        }
        unsigned nz = w.x | w.y | w.z | w.w;
        unsigned anyb = __ballot_sync(FULLMASK, nz != 0u);
        if (!anyb) continue;
        unsigned qu = q + (unsigned)it * step;
        int j = (int)(qu >> 11);
        int cnt = (w.x != 0u) + (w.y != 0u) + (w.z != 0u) + (w.w != 0u);
        int tot = __reduce_add_sync(FULLMASK, cnt);
        if (lane == 0) atomicAdd(&g_degi[j], tot);
        if (nz) {
            unsigned cbase = (qu & 2047u) * 4u;
            unsigned vv[4] = {w.x, w.y, w.z, w.w};
#pragma unroll
            for (int s = 0; s < 4; ++s) {
                if (vv[s]) {
                    unsigned i = cbase + s;
                    int pos = atomicAdd(&g_cnt[i], 1);
                    if (pos < CAP) g_bkt[i * CAP + pos] = j;
                }
            }
        }
    }
}

// ---------------------------------------------------------------
// Kernel 2: fused gather + GEMM + BN-stat epilogue + counter self-clean.
// (unchanged from the 82.7us round)
__global__ void __launch_bounds__(256, 2)
k_gemm(const float* __restrict__ X, const float* __restrict__ bn, const float* __restrict__ bc) {
    extern __shared__ float sh[];
    float* Bs = sh;                  // 16384 floats (64KB) — current weight half
    float* As = sh + CC * CC;        // 4096 floats (16KB) — 32-row A tile

    const int tid  = threadIdx.x;
    const int lane = tid & 31;
    const int wid  = tid >> 5;       // 8 warps
    const int m0   = blockIdx.x * BM;

    {
        const float4* src = (const float4*)g_BT;
        float4* dst = (float4*)Bs;
#pragma unroll
        for (int i = 0; i < 16; ++i) dst[tid + i * 256] = src[tid + i * 256];
    }

    const float4* X4 = (const float4*)X;
#pragma unroll 1
    for (int r = 0; r < 4; ++r) {
        int row  = wid * 4 + r;
        int node = m0 + row;
        int cnt = g_cnt[node]; if (cnt > CAP) cnt = CAP;
        int dg  = g_degi[node];
        float rdeg = (dg > 0) ? (1.f / (float)dg) : 1.f;
        const int* bk = g_bkt + node * CAP;
        int nb[4];
#pragma unroll
        for (int w = 0; w < 4; ++w) nb[w] = (lane + 32 * w < cnt) ? bk[lane + 32 * w] : 0;

        float4 acc = {0.f, 0.f, 0.f, 0.f};
        int t = 0;
        for (; t + 4 <= cnt; t += 4) {
            int j0 = __shfl_sync(FULLMASK, nb[(t + 0) >> 5], (t + 0) & 31);
            int j1 = __shfl_sync(FULLMASK, nb[(t + 1) >> 5], (t + 1) & 31);
            int j2 = __shfl_sync(FULLMASK, nb[(t + 2) >> 5], (t + 2) & 31);
            int j3 = __shfl_sync(FULLMASK, nb[(t + 3) >> 5], (t + 3) & 31);
            float4 x0 = __ldg(X4 + (long)j0 * 32 + lane);
            float4 x1 = __ldg(X4 + (long)j1 * 32 + lane);
            float4 x2 = __ldg(X4 + (long)j2 * 32 + lane);
            float4 x3 = __ldg(X4 + (long)j3 * 32 + lane);
            acc.x += x0.x + x1.x + x2.x + x3.x;
            acc.y += x0.y + x1.y + x2.y + x3.y;
            acc.z += x0.z + x1.z + x2.z + x3.z;
            acc.w += x0.w + x1.w + x2.w + x3.w;
        }
        for (; t < cnt; ++t) {
            int j = __shfl_sync(FULLMASK, nb[t >> 5], t & 31);
            float4 x = __ldg(X4 + (long)j * 32 + lane);
            acc.x += x.x; acc.y += x.y; acc.z += x.z; acc.w += x.w;
        }
        acc.x *= rdeg; acc.y *= rdeg; acc.z *= rdeg; acc.w *= rdeg;
        *(float4*)(As + (size_t)row * CC + lane * 4) = acc;
    }
    if (lane < 4) {
        int node = m0 + wid * 4 + lane;
        g_cnt[node] = 0;
        g_degi[node] = 0;
    }
    __syncthreads();

    const int cg = tid & 31;
    const int rg = tid >> 5;
    unsigned long long acc[4][2];
#pragma unroll
    for (int r = 0; r < 4; ++r) { acc[r][0] = 0ull; acc[r][1] = 0ull; }

#pragma unroll 1
    for (int half = 0; half < 2; ++half) {
        const float* bb = Bs + cg * 4;
        const float* ab = As + rg * 4 * CC;
#pragma unroll 2
        for (int kk = 0; kk < CC; kk += 4) {
            float4 a[4];
#pragma unroll
            for (int r = 0; r < 4; ++r) a[r] = *(const float4*)(ab + r * CC + kk);
#pragma unroll
            for (int j = 0; j < 4; ++j) {
                ulonglong2 bp = *(const ulonglong2*)(bb + (kk + j) * CC);
                float av[4];
#pragma unroll
                for (int r = 0; r < 4; ++r)
                    av[r] = (j == 0) ? a[r].x : (j == 1) ? a[r].y : (j == 2) ? a[r].z : a[r].w;
#pragma unroll
                for (int r = 0; r < 4; ++r) {
                    unsigned long long ad = pack2(av[r]);
                    ffma2(acc[r][0], ad, bp.x);
                    ffma2(acc[r][1], ad, bp.y);
                }
            }
        }
        if (half == 0) {
            __syncthreads();
            const float4* wsrc = (const float4*)(g_BT + CC * CC);
            float4* wdst = (float4*)Bs;
#pragma unroll
            for (int i = 0; i < 16; ++i) wdst[tid + i * 256] = wsrc[tid + i * 256];
            const float4* xs = (const float4*)(X + (size_t)m0 * CC);
            float4* ad = (float4*)As;
#pragma unroll
            for (int i = 0; i < 4; ++i) ad[tid + i * 256] = __ldg(xs + tid + i * 256);
            __syncthreads();
        }
    }

    __syncthreads();
    float* s_sum = sh;
    float* s_sq  = sh + CC;
    if (tid < CC) { s_sum[tid] = 0.f; s_sq[tid] = 0.f; }
    __syncthreads();

    float bias[4];
#pragma unroll
    for (int c = 0; c < 4; ++c) bias[c] = __ldg(bn + cg * 4 + c) + __ldg(bc + cg * 4 + c);

    float psum[4] = {0, 0, 0, 0};
    float psq[4]  = {0, 0, 0, 0};
#pragma unroll
    for (int r = 0; r < 4; ++r) {
        int m = m0 + rg * 4 + r;
        float2 p0 = *(float2*)&acc[r][0];
        float2 p1 = *(float2*)&acc[r][1];
        float h[4] = {p0.x + bias[0], p0.y + bias[1], p1.x + bias[2], p1.y + bias[3]};
#pragma unroll
        for (int c = 0; c < 4; ++c) { psum[c] += h[c]; psq[c] += h[c] * h[c]; }
        float4 hv = {h[0], h[1], h[2], h[3]};
        *(float4*)(g_h + (size_t)m * CC + cg * 4) = hv;
    }
#pragma unroll
    for (int c = 0; c < 4; ++c) {
        atomicAdd(&s_sum[cg * 4 + c], psum[c]);
        atomicAdd(&s_sq[cg * 4 + c],  psq[c]);
    }
    __syncthreads();
    if (tid < CC) {
        atomicAdd(&g_sum[tid],   s_sum[tid]);
        atomicAdd(&g_sumsq[tid], s_sq[tid]);
    }
}

// ---------------------------------------------------------------
// Kernel 3: per-block scale/shift from BN stats (L2-hot) + normalize.
__global__ void k_norm(const float* __restrict__ gamma, const float* __restrict__ beta,
                       float* __restrict__ out) {
    __shared__ float s_sc[CC], s_sf[CC];
    const int tid = threadIdx.x;
    if (tid < CC) {
        const float invN = 1.f / (float)NN;
        float mu  = g_sum[tid] * invN;
        float var = fmaxf(g_sumsq[tid] * invN - mu * mu, 0.f);
        float inv = rsqrtf(var + 1e-5f);
        float sc = __ldg(gamma + tid) * inv;
        s_sc[tid] = sc;
        s_sf[tid] = __ldg(beta + tid) - mu * sc;
    }
    __syncthreads();

    const int gtid = blockIdx.x * blockDim.x + tid;
    const int c0 = (gtid & 31) * 4;
    float4 sc = *(const float4*)(s_sc + c0);
    float4 sf = *(const float4*)(s_sf + c0);
    const float4* hp = (const float4*)g_h;
    float4* op = (float4*)out;
#pragma unroll
    for (int u = 0; u < 2; ++u) {
        int idx = gtid + u * 131072;
        float4 h = __ldcs(hp + idx);
        float4 o;
        o.x = fmaxf(fmaf(h.x, sc.x, sf.x), 0.f);
        o.y = fmaxf(fmaf(h.y, sc.y, sf.y), 0.f);
        o.z = fmaxf(fmaf(h.z, sc.z, sf.z), 0.f);
        o.w = fmaxf(fmaf(h.w, sc.w, sf.w), 0.f);
        op[idx] = o;
    }
}

// ---------------------------------------------------------------
extern "C" void kernel_launch(void* const* d_in, const int* in_sizes, int n_in,
                              void* d_out, int out_size) {
    const float* Xf    = (const float*)d_in[0];
    const float* A     = (const float*)d_in[1];
    const float* Wn    = (const float*)d_in[2];
    const float* bn    = (const float*)d_in[3];
    const float* Wc    = (const float*)d_in[4];
    const float* bc    = (const float*)d_in[5];
    const float* gamma = (const float*)d_in[6];
    const float* beta  = (const float*)d_in[7];
    if (in_sizes[0] > in_sizes[1]) { const float* t = Xf; Xf = A; A = t; }

    float* out = (float*)d_out;

    static bool attr_done = []() {
        size_t smem = (size_t)(CC * CC + BM * CC) * sizeof(float);   // 80KB
        cudaFuncSetAttribute(k_gemm, cudaFuncAttributeMaxDynamicSharedMemorySize, (int)smem);
        return true;
    }();
    (void)attr_done;

    const size_t smem = (size_t)(CC * CC + BM * CC) * sizeof(float);

    k_scan<<<SCANB + TAILB, 256>>>((const uint4*)A, Wn, Wc);
    k_gemm<<<NN / BM, 256, smem>>>(Xf, bn, bc);
    k_norm<<<512, 256>>>(gamma, beta, out);
}

// round 13
// speedup vs baseline: 1.1731x; 1.1731x over previous
#include <cuda_runtime.h>

#define NN 8192
#define CC 128
#define FULLMASK 0xFFFFFFFFu
#define CAP 128
#define BM 32
#define SCANB 2048

// ---- scratch ----
__device__ float g_h[NN * CC];
__device__ int   g_degi[NN];            // zeroed by k_gemm self-clean (static-init first call)
__device__ int   g_cnt[NN];
__device__ int   g_bkt[NN * CAP];
__device__ float g_BT[2 * CC * CC];     // [Wn^T ; Wc^T], K-major [256][128]
__device__ float g_sum[CC];             // zeroed by k_scan tail block
__device__ float g_sumsq[CC];

__device__ __forceinline__ void ffma2(unsigned long long& d, unsigned long long a, unsigned long long b) {
    asm("fma.rn.f32x2 %0, %1, %2, %0;" : "+l"(d) : "l"(a), "l"(b));
}
__device__ __forceinline__ unsigned long long pack2(float x) {
    unsigned long long r; asm("mov.b64 %0, {%1, %1};" : "=l"(r) : "f"(x)); return r;
}

// ---------------------------------------------------------------
// Kernel 1: scan (blocks 0..2047, R11-proven config) + weight transpose
//           (2048..2079) + BN-stat zeroing (2080).
__global__ void __launch_bounds__(256, 8)
k_scan(const uint4* __restrict__ A4,
       const float* __restrict__ Wn, const float* __restrict__ Wc) {
    if (blockIdx.x >= SCANB) {
        int bid = blockIdx.x - SCANB;
        if (bid == 32) {
            if (threadIdx.x < CC) { g_sum[threadIdx.x] = 0.f; g_sumsq[threadIdx.x] = 0.f; }
            return;
        }
        __shared__ float s[32][33];
        int m = bid >> 4;
        int t = bid & 15;
        int tr = (t >> 2) * 32;
        int tc = (t & 3) * 32;
        const float* src = m ? Wc : Wn;
        float* dst = g_BT + m * CC * CC;
        int x = threadIdx.x & 31;
        int y0 = threadIdx.x >> 5;
#pragma unroll
        for (int dy = 0; dy < 32; dy += 8)
            s[y0 + dy][x] = src[(tr + y0 + dy) * CC + tc + x];
        __syncthreads();
#pragma unroll
        for (int dy = 0; dy < 32; dy += 8)
            dst[(tc + y0 + dy) * CC + tr + x] = s[x][y0 + dy];
        return;
    }

    const int lane = threadIdx.x & 31;
    const unsigned stride = SCANB * 256u;      // 524288 uint4
    unsigned q0 = blockIdx.x * 256u + threadIdx.x;

#pragma unroll 1
    for (int it = 0; it < 8; ++it, q0 += 4u * stride) {
        uint4 v[4];
#pragma unroll
        for (int u = 0; u < 4; ++u) v[u] = __ldcs(&A4[q0 + u * stride]);
#pragma unroll
        for (int u = 0; u < 4; ++u) {
            unsigned nz = v[u].x | v[u].y | v[u].z | v[u].w;
            unsigned anyb = __ballot_sync(FULLMASK, nz != 0u);
            if (!anyb) continue;
            unsigned qu = q0 + u * stride;
            int j = (int)(qu >> 11);
            int cnt = (v[u].x != 0u) + (v[u].y != 0u) + (v[u].z != 0u) + (v[u].w != 0u);
            int tot = __reduce_add_sync(FULLMASK, cnt);
            if (lane == 0) atomicAdd(&g_degi[j], tot);
            if (nz) {
                unsigned cbase = (qu & 2047u) * 4u;
                unsigned vv[4] = {v[u].x, v[u].y, v[u].z, v[u].w};
#pragma unroll
                for (int s = 0; s < 4; ++s) {
                    if (vv[s]) {
                        unsigned i = cbase + s;
                        int pos = atomicAdd(&g_cnt[i], 1);
                        if (pos < CAP) g_bkt[i * CAP + pos] = j;
                    }
                }
            }
        }
    }
}

// ---------------------------------------------------------------
// Kernel 2: fused gather + GEMM + BN-stat epilogue + counter self-clean.
// Gather now processes row PAIRS with 8 concurrent loads (MLP 8).
__global__ void __launch_bounds__(256, 2)
k_gemm(const float* __restrict__ X, const float* __restrict__ bn, const float* __restrict__ bc) {
    extern __shared__ float sh[];
    float* Bs = sh;                  // 16384 floats (64KB) — current weight half
    float* As = sh + CC * CC;        // 4096 floats (16KB) — 32-row A tile

    const int tid  = threadIdx.x;
    const int lane = tid & 31;
    const int wid  = tid >> 5;       // 8 warps
    const int m0   = blockIdx.x * BM;

    {
        const float4* src = (const float4*)g_BT;
        float4* dst = (float4*)Bs;
#pragma unroll
        for (int i = 0; i < 16; ++i) dst[tid + i * 256] = src[tid + i * 256];
    }

    // --- gather: warp handles rows wid*4..+3, two rows at a time (MLP 8) ---
    const float4* X4 = (const float4*)X;
#pragma unroll 1
    for (int rp = 0; rp < 4; rp += 2) {
        const int rowA = wid * 4 + rp, rowB = rowA + 1;
        const int nodeA = m0 + rowA,   nodeB = m0 + rowB;
        int cA = g_cnt[nodeA]; cA = cA > CAP ? CAP : cA;
        int cB = g_cnt[nodeB]; cB = cB > CAP ? CAP : cB;
        int dA = g_degi[nodeA], dB = g_degi[nodeB];
        float rA = (dA > 0) ? (1.f / (float)dA) : 1.f;
        float rB = (dB > 0) ? (1.f / (float)dB) : 1.f;
        const int* bkA = g_bkt + nodeA * CAP;
        const int* bkB = g_bkt + nodeB * CAP;

        int nbA[4], nbB[4];
#pragma unroll
        for (int w = 0; w < 4; ++w) {
            nbA[w] = (lane + 32 * w < cA) ? bkA[lane + 32 * w] : 0;
            nbB[w] = (lane + 32 * w < cB) ? bkB[lane + 32 * w] : 0;
        }

        float4 aA = {0.f, 0.f, 0.f, 0.f};
        float4 aB = {0.f, 0.f, 0.f, 0.f};
        const int mm = (cA < cB ? cA : cB) & ~3;
        int t = 0;
        for (; t < mm; t += 4) {            // 8 loads in flight
            int ja0 = __shfl_sync(FULLMASK, nbA[(t + 0) >> 5], (t + 0) & 31);
            int ja1 = __shfl_sync(FULLMASK, nbA[(t + 1) >> 5], (t + 1) & 31);
            int ja2 = __shfl_sync(FULLMASK, nbA[(t + 2) >> 5], (t + 2) & 31);
            int ja3 = __shfl_sync(FULLMASK, nbA[(t + 3) >> 5], (t + 3) & 31);
            int jb0 = __shfl_sync(FULLMASK, nbB[(t + 0) >> 5], (t + 0) & 31);
            int jb1 = __shfl_sync(FULLMASK, nbB[(t + 1) >> 5], (t + 1) & 31);
            int jb2 = __shfl_sync(FULLMASK, nbB[(t + 2) >> 5], (t + 2) & 31);
            int jb3 = __shfl_sync(FULLMASK, nbB[(t + 3) >> 5], (t + 3) & 31);
            float4 x0 = __ldg(X4 + (long)ja0 * 32 + lane);
            float4 x1 = __ldg(X4 + (long)ja1 * 32 + lane);
            float4 x2 = __ldg(X4 + (long)ja2 * 32 + lane);
            float4 x3 = __ldg(X4 + (long)ja3 * 32 + lane);
            float4 y0 = __ldg(X4 + (long)jb0 * 32 + lane);
            float4 y1 = __ldg(X4 + (long)jb1 * 32 + lane);
            float4 y2 = __ldg(X4 + (long)jb2 * 32 + lane);
            float4 y3 = __ldg(X4 + (long)jb3 * 32 + lane);
            aA.x += x0.x + x1.x + x2.x + x3.x;
            aA.y += x0.y + x1.y + x2.y + x3.y;
            aA.z += x0.z + x1.z + x2.z + x3.z;
            aA.w += x0.w + x1.w + x2.w + x3.w;
            aB.x += y0.x + y1.x + y2.x + y3.x;
            aB.y += y0.y + y1.y + y2.y + y3.y;
            aB.z += y0.z + y1.z + y2.z + y3.z;
            aB.w += y0.w + y1.w + y2.w + y3.w;
        }
        int tB = t;
        for (; t + 4 <= cA; t += 4) {
            int j0 = __shfl_sync(FULLMASK, nbA[(t + 0) >> 5], (t + 0) & 31);
            int j1 = __shfl_sync(FULLMASK, nbA[(t + 1) >> 5], (t + 1) & 31);
            int j2 = __shfl_sync(FULLMASK, nbA[(t + 2) >> 5], (t + 2) & 31);
            int j3 = __shfl_sync(FULLMASK, nbA[(t + 3) >> 5], (t + 3) & 31);
            float4 x0 = __ldg(X4 + (long)j0 * 32 + lane);
            float4 x1 = __ldg(X4 + (long)j1 * 32 + lane);
            float4 x2 = __ldg(X4 + (long)j2 * 32 + lane);
            float4 x3 = __ldg(X4 + (long)j3 * 32 + lane);
            aA.x += x0.x + x1.x + x2.x + x3.x;
            aA.y += x0.y + x1.y + x2.y + x3.y;
            aA.z += x0.z + x1.z + x2.z + x3.z;
            aA.w += x0.w + x1.w + x2.w + x3.w;
        }
        for (; t < cA; ++t) {
            int j = __shfl_sync(FULLMASK, nbA[t >> 5], t & 31);
            float4 x = __ldg(X4 + (long)j * 32 + lane);
            aA.x += x.x; aA.y += x.y; aA.z += x.z; aA.w += x.w;
        }
        for (; tB + 4 <= cB; tB += 4) {
            int j0 = __shfl_sync(FULLMASK, nbB[(tB + 0) >> 5], (tB + 0) & 31);
            int j1 = __shfl_sync(FULLMASK, nbB[(tB + 1) >> 5], (tB + 1) & 31);
            int j2 = __shfl_sync(FULLMASK, nbB[(tB + 2) >> 5], (tB + 2) & 31);
            int j3 = __shfl_sync(FULLMASK, nbB[(tB + 3) >> 5], (tB + 3) & 31);
            float4 y0 = __ldg(X4 + (long)j0 * 32 + lane);
            float4 y1 = __ldg(X4 + (long)j1 * 32 + lane);
            float4 y2 = __ldg(X4 + (long)j2 * 32 + lane);
            float4 y3 = __ldg(X4 + (long)j3 * 32 + lane);
            aB.x += y0.x + y1.x + y2.x + y3.x;
            aB.y += y0.y + y1.y + y2.y + y3.y;
            aB.z += y0.z + y1.z + y2.z + y3.z;
            aB.w += y0.w + y1.w + y2.w + y3.w;
        }
        for (; tB < cB; ++tB) {
            int j = __shfl_sync(FULLMASK, nbB[tB >> 5], tB & 31);
            float4 y = __ldg(X4 + (long)j * 32 + lane);
            aB.x += y.x; aB.y += y.y; aB.z += y.z; aB.w += y.w;
        }
        aA.x *= rA; aA.y *= rA; aA.z *= rA; aA.w *= rA;
        aB.x *= rB; aB.y *= rB; aB.z *= rB; aB.w *= rB;
        *(float4*)(As + (size_t)rowA * CC + lane * 4) = aA;
        *(float4*)(As + (size_t)rowB * CC + lane * 4) = aB;
    }
    if (lane < 4) {
        int node = m0 + wid * 4 + lane;
        g_cnt[node] = 0;
        g_degi[node] = 0;
    }
    __syncthreads();

    const int cg = tid & 31;
    const int rg = tid >> 5;
    unsigned long long acc[4][2];
#pragma unroll
    for (int r = 0; r < 4; ++r) { acc[r][0] = 0ull; acc[r][1] = 0ull; }

#pragma unroll 1
    for (int half = 0; half < 2; ++half) {
        const float* bb = Bs + cg * 4;
        const float* ab = As + rg * 4 * CC;
#pragma unroll 2
        for (int kk = 0; kk < CC; kk += 4) {
            float4 a[4];
#pragma unroll
            for (int r = 0; r < 4; ++r) a[r] = *(const float4*)(ab + r * CC + kk);
#pragma unroll
            for (int j = 0; j < 4; ++j) {
                ulonglong2 bp = *(const ulonglong2*)(bb + (kk + j) * CC);
                float av[4];
#pragma unroll
                for (int r = 0; r < 4; ++r)
                    av[r] = (j == 0) ? a[r].x : (j == 1) ? a[r].y : (j == 2) ? a[r].z : a[r].w;
#pragma unroll
                for (int r = 0; r < 4; ++r) {
                    unsigned long long ad = pack2(av[r]);
                    ffma2(acc[r][0], ad, bp.x);
                    ffma2(acc[r][1], ad, bp.y);
                }
            }
        }
        if (half == 0) {
            __syncthreads();
            const float4* wsrc = (const float4*)(g_BT + CC * CC);
            float4* wdst = (float4*)Bs;
#pragma unroll
            for (int i = 0; i < 16; ++i) wdst[tid + i * 256] = wsrc[tid + i * 256];
            const float4* xs = (const float4*)(X + (size_t)m0 * CC);
            float4* ad = (float4*)As;
#pragma unroll
            for (int i = 0; i < 4; ++i) ad[tid + i * 256] = __ldg(xs + tid + i * 256);
            __syncthreads();
        }
    }

    __syncthreads();
    float* s_sum = sh;
    float* s_sq  = sh + CC;
    if (tid < CC) { s_sum[tid] = 0.f; s_sq[tid] = 0.f; }
    __syncthreads();

    float bias[4];
#pragma unroll
    for (int c = 0; c < 4; ++c) bias[c] = __ldg(bn + cg * 4 + c) + __ldg(bc + cg * 4 + c);

    float psum[4] = {0, 0, 0, 0};
    float psq[4]  = {0, 0, 0, 0};
#pragma unroll
    for (int r = 0; r < 4; ++r) {
        int m = m0 + rg * 4 + r;
        float2 p0 = *(float2*)&acc[r][0];
        float2 p1 = *(float2*)&acc[r][1];
        float h[4] = {p0.x + bias[0], p0.y + bias[1], p1.x + bias[2], p1.y + bias[3]};
#pragma unroll
        for (int c = 0; c < 4; ++c) { psum[c] += h[c]; psq[c] += h[c] * h[c]; }
        float4 hv = {h[0], h[1], h[2], h[3]};
        *(float4*)(g_h + (size_t)m * CC + cg * 4) = hv;
    }
#pragma unroll
    for (int c = 0; c < 4; ++c) {
        atomicAdd(&s_sum[cg * 4 + c], psum[c]);
        atomicAdd(&s_sq[cg * 4 + c],  psq[c]);
    }
    __syncthreads();
    if (tid < CC) {
        atomicAdd(&g_sum[tid],   s_sum[tid]);
        atomicAdd(&g_sumsq[tid], s_sq[tid]);
    }
}

// ---------------------------------------------------------------
// Kernel 3: per-block scale/shift from BN stats (L2-hot) + normalize.
__global__ void k_norm(const float* __restrict__ gamma, const float* __restrict__ beta,
                       float* __restrict__ out) {
    __shared__ float s_sc[CC], s_sf[CC];
    const int tid = threadIdx.x;
    if (tid < CC) {
        const float invN = 1.f / (float)NN;
        float mu  = g_sum[tid] * invN;
        float var = fmaxf(g_sumsq[tid] * invN - mu * mu, 0.f);
        float inv = rsqrtf(var + 1e-5f);
        float sc = __ldg(gamma + tid) * inv;
        s_sc[tid] = sc;
        s_sf[tid] = __ldg(beta + tid) - mu * sc;
    }
    __syncthreads();

    const int gtid = blockIdx.x * blockDim.x + tid;
    const int c0 = (gtid & 31) * 4;
    float4 sc = *(const float4*)(s_sc + c0);
    float4 sf = *(const float4*)(s_sf + c0);
    const float4* hp = (const float4*)g_h;
    float4* op = (float4*)out;
#pragma unroll
    for (int u = 0; u < 2; ++u) {
        int idx = gtid + u * 131072;
        float4 h = __ldcs(hp + idx);
        float4 o;
        o.x = fmaxf(fmaf(h.x, sc.x, sf.x), 0.f);
        o.y = fmaxf(fmaf(h.y, sc.y, sf.y), 0.f);
        o.z = fmaxf(fmaf(h.z, sc.z, sf.z), 0.f);
        o.w = fmaxf(fmaf(h.w, sc.w, sf.w), 0.f);
        op[idx] = o;
    }
}

// ---------------------------------------------------------------
extern "C" void kernel_launch(void* const* d_in, const int* in_sizes, int n_in,
                              void* d_out, int out_size) {
    const float* Xf    = (const float*)d_in[0];
    const float* A     = (const float*)d_in[1];
    const float* Wn    = (const float*)d_in[2];
    const float* bn    = (const float*)d_in[3];
    const float* Wc    = (const float*)d_in[4];
    const float* bc    = (const float*)d_in[5];
    const float* gamma = (const float*)d_in[6];
    const float* beta  = (const float*)d_in[7];
    if (in_sizes[0] > in_sizes[1]) { const float* t = Xf; Xf = A; A = t; }

    float* out = (float*)d_out;

    static bool attr_done = []() {
        size_t smem = (size_t)(CC * CC + BM * CC) * sizeof(float);   // 80KB
        cudaFuncSetAttribute(k_gemm, cudaFuncAttributeMaxDynamicSharedMemorySize, (int)smem);
        return true;
    }();
    (void)attr_done;

    const size_t smem = (size_t)(CC * CC + BM * CC) * sizeof(float);

    k_scan<<<SCANB + 33, 256>>>((const uint4*)A, Wn, Wc);
    k_gemm<<<NN / BM, 256, smem>>>(Xf, bn, bc);
    k_norm<<<512, 256>>>(gamma, beta, out);
}